// round 10
// baseline (speedup 1.0000x reference)
#include <cuda_runtime.h>
#include <cuda_fp16.h>

// SmileMoENorm — R6 core + 2-tokens-per-warp software pipeline.
//
// Evidence so far: main kernel pinned at ~83% DRAM; more warps (R5/R8) and
// wider accesses (R7) don't move it. The untried lever: per-warp read DUTY
// CYCLE. Each warp now owns two consecutive tokens; during token A's
// epilogue, each v[k] register is re-used as the load target for token B's
// row immediately after A consumes it, so B's loads are in flight behind
// A's compute. Same register footprint (32 data regs), same occupancy.

#define N_TOKENS    131072
#define HIDDEN      1024
#define NUM_EXPERTS 8
#define H4          (HIDDEN / 4)
#define EPS         1e-5f

__device__ __half2 d_pk[NUM_EXPERTS * HIDDEN];   // (gamma, beta) per element

// ---- pre-pass: pack gamma/beta into fp16 (vectorized) ----------------------
__global__ void k_pack(const float4* __restrict__ gamma4,
                       const float4* __restrict__ beta4) {
    cudaTriggerProgrammaticLaunchCompletion();
    const int i = blockIdx.x * blockDim.x + threadIdx.x;   // 0..2047
    const float4 g = gamma4[i];
    const float4 b = beta4[i];
    __half2* dst = d_pk + i * 4;
    dst[0] = __floats2half2_rn(g.x, b.x);
    dst[1] = __floats2half2_rn(g.y, b.y);
    dst[2] = __floats2half2_rn(g.z, b.z);
    dst[3] = __floats2half2_rn(g.w, b.w);
}

// ---- router helper: top-2 of 8, renormalized softmax -----------------------
__device__ __forceinline__ void route8(float4 la, float4 lb,
                                       int& e0, int& e1,
                                       __half2& w0h, __half2& w1h) {
    float l[NUM_EXPERTS] = { la.x, la.y, la.z, la.w, lb.x, lb.y, lb.z, lb.w };
    float best = l[0], second = -3.4e38f;
    e0 = 0; e1 = 0;
    #pragma unroll
    for (int i = 1; i < NUM_EXPERTS; i++) {
        float v = l[i];
        if (v > best)        { second = best; e1 = e0; best = v; e0 = i; }
        else if (v > second) { second = v; e1 = i; }
    }
    const float w0 = 1.0f / (1.0f + __expf(second - best));
    w0h = __float2half2_rn(w0);
    w1h = __float2half2_rn(1.0f - w0);
}

// ---- stats from v[8] via warp reduction ------------------------------------
__device__ __forceinline__ void stats8(const float4* v, float& rstd, float& mr) {
    float sum = 0.0f, sq = 0.0f;
    #pragma unroll
    for (int k = 0; k < 8; k++) {
        sum += v[k].x + v[k].y + v[k].z + v[k].w;
        sq = fmaf(v[k].x, v[k].x, sq); sq = fmaf(v[k].y, v[k].y, sq);
        sq = fmaf(v[k].z, v[k].z, sq); sq = fmaf(v[k].w, v[k].w, sq);
    }
    #pragma unroll
    for (int off = 16; off > 0; off >>= 1) {
        sum += __shfl_xor_sync(0xFFFFFFFFu, sum, off);
        sq  += __shfl_xor_sync(0xFFFFFFFFu, sq,  off);
    }
    const float mean = sum * (1.0f / HIDDEN);
    const float var  = fmaf(-mean, mean, sq * (1.0f / HIDDEN));
    rstd = rsqrtf(var + EPS);
    mr   = -mean * rstd;
}

// ---- one element-quad of the epilogue ---------------------------------------
__device__ __forceinline__ float4 apply4(float4 xv, float rstd, float mr,
                                         const __half2* pk0, const __half2* pk1,
                                         __half2 w0h, __half2 w1h, int h) {
    const uint4 r0 = *(const uint4*)(pk0 + h);
    const uint4 r1 = *(const uint4*)(pk1 + h);
    __half2 a, b; float2 fb; float4 o;
    a = *(const __half2*)&r0.x; b = *(const __half2*)&r1.x;
    fb = __half22float2(__hfma2(a, w0h, __hmul2(b, w1h)));
    o.x = fmaf(fmaf(xv.x, rstd, mr), fb.x, fb.y);
    a = *(const __half2*)&r0.y; b = *(const __half2*)&r1.y;
    fb = __half22float2(__hfma2(a, w0h, __hmul2(b, w1h)));
    o.y = fmaf(fmaf(xv.y, rstd, mr), fb.x, fb.y);
    a = *(const __half2*)&r0.z; b = *(const __half2*)&r1.z;
    fb = __half22float2(__hfma2(a, w0h, __hmul2(b, w1h)));
    o.z = fmaf(fmaf(xv.z, rstd, mr), fb.x, fb.y);
    a = *(const __half2*)&r0.w; b = *(const __half2*)&r1.w;
    fb = __half22float2(__hfma2(a, w0h, __hmul2(b, w1h)));
    o.w = fmaf(fmaf(xv.w, rstd, mr), fb.x, fb.y);
    return o;
}

// ------------------------------------------------------------- main kernel
__global__ __launch_bounds__(256, 4)
void smile_moe_norm_kernel(const float4* __restrict__ x,
                           const float4* __restrict__ logits4,   // [N,2] float4
                           float4* __restrict__ out) {
    const int gw   = blockIdx.x * (blockDim.x >> 5) + (threadIdx.x >> 5);
    const int lane = threadIdx.x & 31;
    const int tA   = gw * 2;          // tokens tA, tA+1
    const int tB   = tA + 1;

    // ---- route both tokens up front (logits are tiny; L2 hits) ------------
    int e0A, e1A, e0B, e1B;
    __half2 w0hA, w1hA, w0hB, w1hB;
    route8(__ldg(&logits4[tA * 2]), __ldg(&logits4[tA * 2 + 1]), e0A, e1A, w0hA, w1hA);
    route8(__ldg(&logits4[tB * 2]), __ldg(&logits4[tB * 2 + 1]), e0B, e1B, w0hB, w1hB);

    // ---- token A: load row + stats -----------------------------------------
    const float4* xrA = x + (size_t)tA * H4;
    const float4* xrB = x + (size_t)tB * H4;
    float4 v[8];
    #pragma unroll
    for (int k = 0; k < 8; k++) v[k] = __ldcs(&xrA[lane + 32 * k]);
    float rstdA, mrA;
    stats8(v, rstdA, mrA);

    cudaGridDependencySynchronize();   // d_pk ready (latency fully hidden)

    // ---- epilogue A, interleaving token B's row loads -----------------------
    const __half2* pk0A = d_pk + e0A * HIDDEN;
    const __half2* pk1A = d_pk + e1A * HIDDEN;
    float4* orowA = out + (size_t)tA * H4;
    #pragma unroll
    for (int k = 0; k < 8; k++) {
        const int h4 = lane + 32 * k;
        const float4 xa = v[k];
        v[k] = __ldcs(&xrB[h4]);        // B's load in flight behind A's math
        const float4 o = apply4(xa, rstdA, mrA, pk0A, pk1A, w0hA, w1hA, 4 * h4);
        __stcs(&orowA[h4], o);
    }

    // ---- token B: stats (loads largely complete) + epilogue -----------------
    float rstdB, mrB;
    stats8(v, rstdB, mrB);
    const __half2* pk0B = d_pk + e0B * HIDDEN;
    const __half2* pk1B = d_pk + e1B * HIDDEN;
    float4* orowB = out + (size_t)tB * H4;
    #pragma unroll
    for (int k = 0; k < 8; k++) {
        const int h4 = lane + 32 * k;
        const float4 o = apply4(v[k], rstdB, mrB, pk0B, pk1B, w0hB, w1hB, 4 * h4);
        __stcs(&orowB[h4], o);
    }
}

// ------------------------------------------------------------------ launch
extern "C" void kernel_launch(void* const* d_in, const int* in_sizes, int n_in,
                              void* d_out, int out_size) {
    const float4* x       = (const float4*)d_in[0];  // hidden_states [N, H]
    const float4* logits4 = (const float4*)d_in[1];  // router_logits [N, 8]
    const float4* gamma4  = (const float4*)d_in[2];  // [E, H]
    const float4* beta4   = (const float4*)d_in[3];  // [E, H]
    float4* out           = (float4*)d_out;

    cudaLaunchAttribute attr[1];
    attr[0].id = cudaLaunchAttributeProgrammaticStreamSerialization;
    attr[0].val.programmaticStreamSerializationAllowed = 1;

    cudaLaunchConfig_t cfgp = {};
    cfgp.gridDim  = dim3(8, 1, 1);
    cfgp.blockDim = dim3(256, 1, 1);
    cfgp.attrs = attr;
    cfgp.numAttrs = 1;
    cudaLaunchKernelEx(&cfgp, k_pack, gamma4, beta4);

    cudaLaunchConfig_t cfg = {};
    cfg.gridDim  = dim3(N_TOKENS / 16, 1, 1);        // 8 warps x 2 tokens
    cfg.blockDim = dim3(256, 1, 1);
    cfg.attrs = attr;
    cfg.numAttrs = 1;
    cudaLaunchKernelEx(&cfg, smile_moe_norm_kernel, x, logits4, out);
}